// round 1
// baseline (speedup 1.0000x reference)
#include <cuda_runtime.h>

// DiffUnpool: out[b] = S[b] @ x[b]
//   S: [16, 2048, 256]  (8388608 f32)
//   x: [16,  256, 256]  (1048576 f32)
//   A: [16, 2048, 2048] (unused)
//   out: [16, 2048, 256]
//
// SIMT fp32 GEMM, 128x128x16 tiles, 256 threads, 8x8 per thread.

#define BM 128
#define BN 128
#define BK 16

__global__ __launch_bounds__(256, 2)
void diffunpool_gemm(const float* __restrict__ S,
                     const float* __restrict__ X,
                     float* __restrict__ O) {
    const int P = 256;   // K dim
    const int C = 256;   // N dim (cols of x)
    const int N = 2048;  // M dim (rows of S)

    const int b  = blockIdx.z;
    const int mt = blockIdx.y;
    const int nt = blockIdx.x;

    const float* Sb = S + (size_t)b * N * P + (size_t)mt * BM * P;
    const float* Xb = X + (size_t)b * P * C + (size_t)nt * BN;
    float*       Ob = O + (size_t)b * N * C + (size_t)mt * BM * C + (size_t)nt * BN;

    // A tile stored k-major: Ss[k][m]; B tile: Xs[k][n]
    __shared__ float Ss[BK][BM];
    __shared__ float Xs[BK][BN];

    const int tid = threadIdx.x;
    const int tx  = tid & 15;   // n-group
    const int ty  = tid >> 4;   // m-group

    float acc[8][8];
    #pragma unroll
    for (int i = 0; i < 8; i++)
        #pragma unroll
        for (int j = 0; j < 8; j++)
            acc[i][j] = 0.0f;

    for (int k0 = 0; k0 < P; k0 += BK) {
        // ---- Load A tile (BM x BK) as float4, store transposed to Ss[k][m]
        // 128*16/4 = 512 float4 loads; 2 per thread.
        #pragma unroll
        for (int i = 0; i < 2; i++) {
            int f   = tid * 2 + i;       // 0..511
            int row = f >> 2;            // 0..127
            int kq  = (f & 3) << 2;      // 0,4,8,12
            float4 v = *(const float4*)(Sb + (size_t)row * P + k0 + kq);
            Ss[kq + 0][row] = v.x;
            Ss[kq + 1][row] = v.y;
            Ss[kq + 2][row] = v.z;
            Ss[kq + 3][row] = v.w;
        }
        // ---- Load B tile (BK x BN) as float4, direct store
        // 16*128/4 = 512 float4 loads; 2 per thread.
        #pragma unroll
        for (int i = 0; i < 2; i++) {
            int f  = tid * 2 + i;
            int kk = f >> 5;             // 0..15
            int nn = (f & 31) << 2;      // 0..124 step 4
            *(float4*)(&Xs[kk][nn]) =
                *(const float4*)(Xb + (size_t)(k0 + kk) * C + nn);
        }
        __syncthreads();

        #pragma unroll
        for (int k = 0; k < BK; k++) {
            float4 a0 = *(const float4*)(&Ss[k][ty * 4]);
            float4 a1 = *(const float4*)(&Ss[k][ty * 4 + 64]);
            float4 b0 = *(const float4*)(&Xs[k][tx * 4]);
            float4 b1 = *(const float4*)(&Xs[k][tx * 4 + 64]);
            float am[8] = {a0.x, a0.y, a0.z, a0.w, a1.x, a1.y, a1.z, a1.w};
            float bn[8] = {b0.x, b0.y, b0.z, b0.w, b1.x, b1.y, b1.z, b1.w};
            #pragma unroll
            for (int i = 0; i < 8; i++)
                #pragma unroll
                for (int j = 0; j < 8; j++)
                    acc[i][j] = fmaf(am[i], bn[j], acc[i][j]);
        }
        __syncthreads();
    }

    // ---- Epilogue: float4 stores
    #pragma unroll
    for (int i = 0; i < 8; i++) {
        int m = (i < 4) ? (ty * 4 + i) : (ty * 4 + 64 + (i - 4));
        float4 v0 = make_float4(acc[i][0], acc[i][1], acc[i][2], acc[i][3]);
        float4 v1 = make_float4(acc[i][4], acc[i][5], acc[i][6], acc[i][7]);
        *(float4*)(Ob + (size_t)m * C + tx * 4)      = v0;
        *(float4*)(Ob + (size_t)m * C + tx * 4 + 64) = v1;
    }
}

extern "C" void kernel_launch(void* const* d_in, const int* in_sizes, int n_in,
                              void* d_out, int out_size) {
    // Identify inputs by element count (robust to ordering):
    //   x: 16*256*256   = 1048576
    //   S: 16*2048*256  = 8388608
    //   A: 16*2048*2048 = 67108864 (unused)
    const float* S = nullptr;
    const float* X = nullptr;
    for (int i = 0; i < n_in; i++) {
        if (in_sizes[i] == 8388608)      S = (const float*)d_in[i];
        else if (in_sizes[i] == 1048576) X = (const float*)d_in[i];
    }
    float* O = (float*)d_out;

    dim3 grid(256 / BN, 2048 / BM, 16);  // (2, 16, 16)
    dim3 block(256);
    diffunpool_gemm<<<grid, block>>>(S, X, O);
}

// round 3
// speedup vs baseline: 1.7758x; 1.7758x over previous
#include <cuda_runtime.h>
#include <cuda_bf16.h>
#include <cstdint>

// DiffUnpool: out[b] = S[b] @ x[b]
//   S: [16, 2048, 256] f32   x: [16, 256, 256] f32   out: [16, 2048, 256] f32
// bf16 hi/lo split on mma.sync.m16n8k16 (base-PTX tensor path; tcgen05 not
// available at the harness's compute_103 PTX target).
// D = Shi*Xhi + Shi*Xlo + Slo*Xhi, fp32 accumulate.

#define BM 128
#define BN 64
#define BK 32
#define A_STRIDE 80      // bytes per A smem row: 32 bf16 = 64B padded to 80 (conflict-free LDSM)
#define B_STRIDE 128     // bytes per B smem row: 64 bf16

// SMEM offsets (16B aligned; A_STRIDE=80 is 16B-multiple)
#define SM_AHI 0
#define SM_ALO (SM_AHI + BM * A_STRIDE)          // 10240
#define SM_BHI (SM_ALO + BM * A_STRIDE)          // 20480
#define SM_BLO (SM_BHI + BK * B_STRIDE)          // 24576
#define SM_TOTAL (SM_BLO + BK * B_STRIDE)        // 28672

static __device__ __forceinline__ uint32_t cvta_smem(const void* p) {
    uint32_t a;
    asm("{ .reg .u64 t; cvta.to.shared.u64 t, %1; cvt.u32.u64 %0, t; }"
        : "=r"(a) : "l"(p));
    return a;
}

#define LDSM_X4(r0, r1, r2, r3, a) \
    asm volatile("ldmatrix.sync.aligned.m8n8.x4.shared.b16 {%0,%1,%2,%3}, [%4];" \
                 : "=r"(r0), "=r"(r1), "=r"(r2), "=r"(r3) : "r"(a))
#define LDSM_X4_T(r0, r1, r2, r3, a) \
    asm volatile("ldmatrix.sync.aligned.m8n8.x4.trans.shared.b16 {%0,%1,%2,%3}, [%4];" \
                 : "=r"(r0), "=r"(r1), "=r"(r2), "=r"(r3) : "r"(a))
#define MMA16816(d, a, b0, b1) \
    asm volatile("mma.sync.aligned.m16n8k16.row.col.f32.bf16.bf16.f32 " \
                 "{%0,%1,%2,%3},{%4,%5,%6,%7},{%8,%9},{%0,%1,%2,%3};" \
                 : "+f"((d)[0]), "+f"((d)[1]), "+f"((d)[2]), "+f"((d)[3]) \
                 : "r"((a)[0]), "r"((a)[1]), "r"((a)[2]), "r"((a)[3]), "r"(b0), "r"(b1))

// split one fp32 into packed bf16 hi/lo halves (two floats -> one u32 each)
static __device__ __forceinline__ void split2(float v0, float v1, uint32_t& hi, uint32_t& lo) {
    __nv_bfloat16 h0 = __float2bfloat16(v0);
    __nv_bfloat16 h1 = __float2bfloat16(v1);
    __nv_bfloat16 l0 = __float2bfloat16(v0 - __bfloat162float(h0));
    __nv_bfloat16 l1 = __float2bfloat16(v1 - __bfloat162float(h1));
    hi = (uint32_t)__bfloat16_as_ushort(h0) | ((uint32_t)__bfloat16_as_ushort(h1) << 16);
    lo = (uint32_t)__bfloat16_as_ushort(l0) | ((uint32_t)__bfloat16_as_ushort(l1) << 16);
}

__global__ __launch_bounds__(256, 2)
void diffunpool_hmma(const float* __restrict__ S, const float* __restrict__ X,
                     float* __restrict__ O) {
    __shared__ __align__(16) char smem[SM_TOTAL];

    const int nt = blockIdx.x;       // 0..3   (N tiles of 64)
    const int mt = blockIdx.y;       // 0..15  (M tiles of 128)
    const int b  = blockIdx.z;       // 0..15

    const float* Sb = S + ((size_t)b * 2048 + (size_t)mt * BM) * 256;
    const float* Xb = X + (size_t)b * 256 * 256 + (size_t)nt * BN;
    float*       Ob = O + ((size_t)b * 2048 + (size_t)mt * BM) * 256 + (size_t)nt * BN;

    const int tid  = threadIdx.x;
    const int wid  = tid >> 5;
    const int lane = tid & 31;
    const int warp_m = (wid & 3) * 32;
    const int warp_n = (wid >> 2) * 32;

    const uint32_t sb = cvta_smem(smem);

    // ---- global load mapping
    // A: row = tid>>1 (0..127), cols (tid&1)*16 .. +15  (4 float4)
    // B: row = tid>>3 (0..31),  cols (tid&7)*8  .. +7   (2 float4)
    const int arow = tid >> 1, acol = (tid & 1) * 16;
    const int brow = tid >> 3, bcol = (tid & 7) * 8;
    const float* pA = Sb + (size_t)arow * 256 + acol;
    const float* pB = Xb + (size_t)brow * 256 + bcol;

    // ---- A smem store offsets
    uint32_t aoff0 = sb + (uint32_t)arow * A_STRIDE + acol * 2;       // hi/lo base added later
    // ---- B smem store offset (swizzled chunk)
    uint32_t bchunk = (uint32_t)(tid & 7);
    uint32_t boff = sb + (uint32_t)brow * B_STRIDE + ((bchunk ^ (brow & 7)) << 4);

    // ---- ldmatrix lane addresses (precomputed per thread)
    // A frag (m0, k0): row = m0 + (lane&15); k = k0 + (lane>>4)*8
    uint32_t a_lrow = (uint32_t)(warp_m + (lane & 15));
    uint32_t a_lk   = (uint32_t)((lane >> 4) * 8);
    // addr(i, k0, base) = base + (a_lrow + 16i)*80 + (k0 + a_lk)*2
    // B frag block (k0, n0): row = k0 + (lane&15... see mapping); chunk = n0/8 + (lane>>4)
    uint32_t b_lrow = (uint32_t)(lane & 15);
    uint32_t b_lc   = (uint32_t)((warp_n >> 3) + (lane >> 4));

    float d[2][4][4];   // [m frag][n8 frag][reg]
#pragma unroll
    for (int i = 0; i < 2; i++)
#pragma unroll
        for (int j = 0; j < 4; j++)
#pragma unroll
            for (int r = 0; r < 4; r++) d[i][j][r] = 0.0f;

    float4 rA[4], rB[2];
    // prologue: chunk 0
#pragma unroll
    for (int g = 0; g < 4; g++) rA[g] = *(const float4*)(pA + g * 4);
#pragma unroll
    for (int g = 0; g < 2; g++) rB[g] = *(const float4*)(pB + g * 4);

    for (int c = 0; c < 8; c++) {
        // ---- convert + store to smem
#pragma unroll
        for (int g = 0; g < 2; g++) {   // two 8-float groups of A
            float v[8] = {rA[2*g].x, rA[2*g].y, rA[2*g].z, rA[2*g].w,
                          rA[2*g+1].x, rA[2*g+1].y, rA[2*g+1].z, rA[2*g+1].w};
            uint32_t h[4], l[4];
#pragma unroll
            for (int q = 0; q < 4; q++) split2(v[2*q], v[2*q+1], h[q], l[q]);
            uint32_t off = aoff0 + g * 16;
            *(uint4*)(smem + (off - sb) + SM_AHI) = make_uint4(h[0], h[1], h[2], h[3]);
            *(uint4*)(smem + (off - sb) + SM_ALO) = make_uint4(l[0], l[1], l[2], l[3]);
        }
        {
            float v[8] = {rB[0].x, rB[0].y, rB[0].z, rB[0].w,
                          rB[1].x, rB[1].y, rB[1].z, rB[1].w};
            uint32_t h[4], l[4];
#pragma unroll
            for (int q = 0; q < 4; q++) split2(v[2*q], v[2*q+1], h[q], l[q]);
            *(uint4*)(smem + (boff - sb) + SM_BHI) = make_uint4(h[0], h[1], h[2], h[3]);
            *(uint4*)(smem + (boff - sb) + SM_BLO) = make_uint4(l[0], l[1], l[2], l[3]);
        }
        __syncthreads();

        // ---- prefetch next chunk's globals
        if (c < 7) {
#pragma unroll
            for (int g = 0; g < 4; g++)
                rA[g] = *(const float4*)(pA + (c + 1) * 32 + g * 4);
#pragma unroll
            for (int g = 0; g < 2; g++)
                rB[g] = *(const float4*)(pB + (size_t)(c + 1) * 32 * 256 + g * 4);
        }

        // ---- compute: 2 k16 steps, 3 products each
#pragma unroll
        for (int kk = 0; kk < 2; kk++) {
            const uint32_t k0 = kk * 16;
            uint32_t ah[2][4], al[2][4], bh[2][4], bl[2][4];
#pragma unroll
            for (int i = 0; i < 2; i++) {
                uint32_t aaddr = sb + (a_lrow + i * 16) * A_STRIDE + (k0 + a_lk) * 2;
                LDSM_X4(ah[i][0], ah[i][1], ah[i][2], ah[i][3], aaddr + SM_AHI);
                LDSM_X4(al[i][0], al[i][1], al[i][2], al[i][3], aaddr + SM_ALO);
            }
#pragma unroll
            for (int nb = 0; nb < 2; nb++) {
                uint32_t row = k0 + b_lrow;
                uint32_t ch  = (b_lc + nb * 2) ^ (row & 7);
                uint32_t baddr = sb + row * B_STRIDE + (ch << 4);
                LDSM_X4_T(bh[nb][0], bh[nb][1], bh[nb][2], bh[nb][3], baddr + SM_BHI);
                LDSM_X4_T(bl[nb][0], bl[nb][1], bl[nb][2], bl[nb][3], baddr + SM_BLO);
            }
#pragma unroll
            for (int i = 0; i < 2; i++)
#pragma unroll
                for (int nb = 0; nb < 2; nb++) {
                    MMA16816(d[i][2*nb],   ah[i], bh[nb][0], bh[nb][1]);   // Shi*Xhi
                    MMA16816(d[i][2*nb+1], ah[i], bh[nb][2], bh[nb][3]);
                    MMA16816(d[i][2*nb],   ah[i], bl[nb][0], bl[nb][1]);   // Shi*Xlo
                    MMA16816(d[i][2*nb+1], ah[i], bl[nb][2], bl[nb][3]);
                    MMA16816(d[i][2*nb],   al[i], bh[nb][0], bh[nb][1]);   // Slo*Xhi
                    MMA16816(d[i][2*nb+1], al[i], bh[nb][2], bh[nb][3]);
                }
        }
        __syncthreads();
    }

    // ---- epilogue: write 32x32 warp tile
    const int group = lane >> 2;
    const int tcol  = (lane & 3) * 2;
#pragma unroll
    for (int i = 0; i < 2; i++) {
        int m0 = warp_m + i * 16 + group;
#pragma unroll
        for (int j = 0; j < 4; j++) {
            int n0 = warp_n + j * 8 + tcol;
            *(float2*)(Ob + (size_t)m0 * 256 + n0)       = make_float2(d[i][j][0], d[i][j][1]);
            *(float2*)(Ob + (size_t)(m0 + 8) * 256 + n0) = make_float2(d[i][j][2], d[i][j][3]);
        }
    }
}

extern "C" void kernel_launch(void* const* d_in, const int* in_sizes, int n_in,
                              void* d_out, int out_size) {
    const float* S = nullptr;
    const float* X = nullptr;
    for (int i = 0; i < n_in; i++) {
        if (in_sizes[i] == 8388608)      S = (const float*)d_in[i];
        else if (in_sizes[i] == 1048576) X = (const float*)d_in[i];
    }
    float* O = (float*)d_out;

    dim3 grid(256 / BN, 2048 / BM, 16);   // (4, 16, 16)
    diffunpool_hmma<<<grid, 256>>>(S, X, O);
}